// round 1
// baseline (speedup 1.0000x reference)
#include <cuda_runtime.h>
#include <math.h>

#define M_TOK   8192      // 4 * 2048 tokens
#define DMODEL  2048
#define NHEADS  16
#define HDIM    128
#define SEQ     2048
#define BATCH   4

// ---------------- scratch (static device allocations; no cudaMalloc) -------
__device__ float g_q[(size_t)M_TOK * DMODEL];
__device__ float g_k[(size_t)M_TOK * DMODEL];
__device__ float g_v[(size_t)M_TOK * DMODEL];
__device__ float g_ctx[(size_t)M_TOK * DMODEL];

// ---------------------------------------------------------------------------
// SGEMM: C[m][n] = sum_k A[m][k] * B[n][k]  (+ bias[n] if bias != nullptr)
// A: [M,K] row-major, B: [N,K] row-major (torch Linear weight layout).
// Tiles: 128x128x16, 256 threads, 8x8 per-thread register blocking.
// M % 128 == 0, N % 128 == 0, K % 16 == 0 assumed (true for this problem).
// ---------------------------------------------------------------------------
__global__ __launch_bounds__(256)
void sgemm_tn(const float* __restrict__ A, const float* __restrict__ B,
              float* __restrict__ C, const float* __restrict__ bias,
              int M, int N, int K)
{
    __shared__ __align__(16) float As[16][132];
    __shared__ __align__(16) float Bs[16][132];

    const int tid = threadIdx.x;
    const int tx = tid & 15;        // n dimension
    const int ty = tid >> 4;        // m dimension

    const float* Ab = A + (size_t)blockIdx.y * 128 * K;
    const float* Bb = B + (size_t)blockIdx.x * 128 * K;

    float acc[8][8];
#pragma unroll
    for (int i = 0; i < 8; ++i)
#pragma unroll
        for (int j = 0; j < 8; ++j) acc[i][j] = 0.0f;

    for (int k0 = 0; k0 < K; k0 += 16) {
        // stage A,B tiles (transposed: [k][m] / [k][n])
#pragma unroll
        for (int it = 0; it < 2; ++it) {
            int f   = tid + it * 256;       // float4 id, 512 total per matrix
            int row = f >> 2;               // 0..127
            int kc  = (f & 3) << 2;         // 0,4,8,12
            float4 va = *(const float4*)(Ab + (size_t)row * K + k0 + kc);
            As[kc + 0][row] = va.x; As[kc + 1][row] = va.y;
            As[kc + 2][row] = va.z; As[kc + 3][row] = va.w;
            float4 vb = *(const float4*)(Bb + (size_t)row * K + k0 + kc);
            Bs[kc + 0][row] = vb.x; Bs[kc + 1][row] = vb.y;
            Bs[kc + 2][row] = vb.z; Bs[kc + 3][row] = vb.w;
        }
        __syncthreads();

#pragma unroll
        for (int kk = 0; kk < 16; ++kk) {
            float a[8], b[8];
            *(float4*)&a[0] = *(const float4*)&As[kk][ty * 8];
            *(float4*)&a[4] = *(const float4*)&As[kk][ty * 8 + 4];
            *(float4*)&b[0] = *(const float4*)&Bs[kk][tx * 8];
            *(float4*)&b[4] = *(const float4*)&Bs[kk][tx * 8 + 4];
#pragma unroll
            for (int i = 0; i < 8; ++i)
#pragma unroll
                for (int j = 0; j < 8; ++j)
                    acc[i][j] += a[i] * b[j];
        }
        __syncthreads();
    }

    // epilogue
    const int n0 = blockIdx.x * 128 + tx * 8;
    float bv[8];
#pragma unroll
    for (int j = 0; j < 8; ++j) bv[j] = bias ? bias[n0 + j] : 0.0f;

#pragma unroll
    for (int i = 0; i < 8; ++i) {
        int m = blockIdx.y * 128 + ty * 8 + i;
        float* Cp = C + (size_t)m * N + n0;
        float4 o0, o1;
        o0.x = acc[i][0] + bv[0]; o0.y = acc[i][1] + bv[1];
        o0.z = acc[i][2] + bv[2]; o0.w = acc[i][3] + bv[3];
        o1.x = acc[i][4] + bv[4]; o1.y = acc[i][5] + bv[5];
        o1.z = acc[i][6] + bv[6]; o1.w = acc[i][7] + bv[7];
        *(float4*)(Cp)     = o0;
        *(float4*)(Cp + 4) = o1;
    }
}

// ---------------------------------------------------------------------------
// Flash attention (fp32, causal). One CTA per (q-tile of 64, head, batch).
// q/k/v stored as [token, DMODEL]; head h occupies columns [h*128, h*128+128).
// BQ = BK = 64, D = 128, 256 threads (16x16), 4x4 S tile per thread.
// Online softmax; P staged through smem for the PV GEMM.
// ---------------------------------------------------------------------------
#define QS_STRIDE 132
#define PS_STRIDE 68
#define FA_SMEM_FLOATS (3 * 64 * QS_STRIDE + 64 * PS_STRIDE)

__global__ __launch_bounds__(256)
void flash_attn(const float* __restrict__ Q, const float* __restrict__ K,
                const float* __restrict__ V, float* __restrict__ O)
{
    extern __shared__ float sm[];
    float* Qs = sm;                       // 64 x 132
    float* Ks = Qs + 64 * QS_STRIDE;      // 64 x 132
    float* Vs = Ks + 64 * QS_STRIDE;      // 64 x 132
    float* Ps = Vs + 64 * QS_STRIDE;      // 64 x 68

    const int tid = threadIdx.x;
    const int tx = tid & 15;              // k-col group / d-col group
    const int ty = tid >> 4;              // q-row group

    const int qt = blockIdx.x;            // q tile (0..31)
    const int h  = blockIdx.y;
    const int b  = blockIdx.z;

    const size_t base = (size_t)b * SEQ * DMODEL + (size_t)h * HDIM;
    const float scale = 0.08838834764831845f;   // 1/sqrt(128)

    // load Q tile: 64 rows x 128 cols = 2048 float4, 8 per thread
#pragma unroll
    for (int it = 0; it < 8; ++it) {
        int f   = tid + it * 256;
        int row = f >> 5;                 // 32 float4 per row
        int col = (f & 31) << 2;
        *(float4*)&Qs[row * QS_STRIDE + col] =
            *(const float4*)(Q + base + (size_t)(qt * 64 + row) * DMODEL + col);
    }

    float mrow[4], lrow[4], o[4][8];
#pragma unroll
    for (int i = 0; i < 4; ++i) {
        mrow[i] = -1e30f; lrow[i] = 0.0f;
#pragma unroll
        for (int c = 0; c < 8; ++c) o[i][c] = 0.0f;
    }

    for (int kt = 0; kt <= qt; ++kt) {
        __syncthreads();    // previous PV done (and Qs visible on first iter)
        // load K,V tiles
#pragma unroll
        for (int it = 0; it < 8; ++it) {
            int f   = tid + it * 256;
            int row = f >> 5;
            int col = (f & 31) << 2;
            size_t g = base + (size_t)(kt * 64 + row) * DMODEL + col;
            *(float4*)&Ks[row * QS_STRIDE + col] = *(const float4*)(K + g);
            *(float4*)&Vs[row * QS_STRIDE + col] = *(const float4*)(V + g);
        }
        __syncthreads();

        // S = Q K^T : 4x4 per thread over d=128
        float s[4][4];
#pragma unroll
        for (int i = 0; i < 4; ++i)
#pragma unroll
            for (int j = 0; j < 4; ++j) s[i][j] = 0.0f;

        for (int d = 0; d < 128; d += 4) {
            float4 qa[4], kb[4];
#pragma unroll
            for (int i = 0; i < 4; ++i)
                qa[i] = *(const float4*)&Qs[(ty * 4 + i) * QS_STRIDE + d];
#pragma unroll
            for (int j = 0; j < 4; ++j)
                kb[j] = *(const float4*)&Ks[(tx * 4 + j) * QS_STRIDE + d];
#pragma unroll
            for (int i = 0; i < 4; ++i)
#pragma unroll
                for (int j = 0; j < 4; ++j) {
                    s[i][j] += qa[i].x * kb[j].x;
                    s[i][j] += qa[i].y * kb[j].y;
                    s[i][j] += qa[i].z * kb[j].z;
                    s[i][j] += qa[i].w * kb[j].w;
                }
        }

        const bool diag = (kt == qt);
#pragma unroll
        for (int i = 0; i < 4; ++i) {
#pragma unroll
            for (int j = 0; j < 4; ++j) {
                s[i][j] *= scale;
                if (diag && (tx * 4 + j) > (ty * 4 + i)) s[i][j] = -1e30f;
            }
            // row max across the 64-wide tile (lane bits 0..3 = tx)
            float mt = fmaxf(fmaxf(s[i][0], s[i][1]), fmaxf(s[i][2], s[i][3]));
            mt = fmaxf(mt, __shfl_xor_sync(0xffffffffu, mt, 1));
            mt = fmaxf(mt, __shfl_xor_sync(0xffffffffu, mt, 2));
            mt = fmaxf(mt, __shfl_xor_sync(0xffffffffu, mt, 4));
            mt = fmaxf(mt, __shfl_xor_sync(0xffffffffu, mt, 8));

            float mnew  = fmaxf(mrow[i], mt);
            float alpha = __expf(mrow[i] - mnew);
            float p0 = __expf(s[i][0] - mnew);
            float p1 = __expf(s[i][1] - mnew);
            float p2 = __expf(s[i][2] - mnew);
            float p3 = __expf(s[i][3] - mnew);
            float rs = p0 + p1 + p2 + p3;
            rs += __shfl_xor_sync(0xffffffffu, rs, 1);
            rs += __shfl_xor_sync(0xffffffffu, rs, 2);
            rs += __shfl_xor_sync(0xffffffffu, rs, 4);
            rs += __shfl_xor_sync(0xffffffffu, rs, 8);

            lrow[i] = lrow[i] * alpha + rs;
            mrow[i] = mnew;
#pragma unroll
            for (int c = 0; c < 8; ++c) o[i][c] *= alpha;

            float* prow = &Ps[(ty * 4 + i) * PS_STRIDE + tx * 4];
            prow[0] = p0; prow[1] = p1; prow[2] = p2; prow[3] = p3;
        }
        __syncthreads();

        // O += P V : per thread rows ty*4+i, cols tx*8 .. +7
#pragma unroll 4
        for (int kc = 0; kc < 64; ++kc) {
            float4 v0 = *(const float4*)&Vs[kc * QS_STRIDE + tx * 8];
            float4 v1 = *(const float4*)&Vs[kc * QS_STRIDE + tx * 8 + 4];
#pragma unroll
            for (int i = 0; i < 4; ++i) {
                float p = Ps[(ty * 4 + i) * PS_STRIDE + kc];
                o[i][0] += p * v0.x; o[i][1] += p * v0.y;
                o[i][2] += p * v0.z; o[i][3] += p * v0.w;
                o[i][4] += p * v1.x; o[i][5] += p * v1.y;
                o[i][6] += p * v1.z; o[i][7] += p * v1.w;
            }
        }
    }

    // epilogue: O /= l, write ctx
#pragma unroll
    for (int i = 0; i < 4; ++i) {
        float inv = 1.0f / lrow[i];
        int row = qt * 64 + ty * 4 + i;
        float* Op = O + base + (size_t)row * DMODEL + tx * 8;
        float4 o0, o1;
        o0.x = o[i][0] * inv; o0.y = o[i][1] * inv;
        o0.z = o[i][2] * inv; o0.w = o[i][3] * inv;
        o1.x = o[i][4] * inv; o1.y = o[i][5] * inv;
        o1.z = o[i][6] * inv; o1.w = o[i][7] * inv;
        *(float4*)(Op)     = o0;
        *(float4*)(Op + 4) = o1;
    }
}

// ---------------------------------------------------------------------------
extern "C" void kernel_launch(void* const* d_in, const int* in_sizes, int n_in,
                              void* d_out, int out_size)
{
    (void)in_sizes; (void)n_in; (void)out_size;
    const float* x  = (const float*)d_in[0];
    const float* Wq = (const float*)d_in[1];
    const float* Wk = (const float*)d_in[2];
    const float* Wv = (const float*)d_in[3];
    const float* Wo = (const float*)d_in[4];
    const float* bo = (const float*)d_in[5];
    float* out = (float*)d_out;

    float *q, *k, *v, *ctx;
    cudaGetSymbolAddress((void**)&q,   g_q);
    cudaGetSymbolAddress((void**)&k,   g_k);
    cudaGetSymbolAddress((void**)&v,   g_v);
    cudaGetSymbolAddress((void**)&ctx, g_ctx);

    dim3 gblk(256);
    dim3 ggrid(DMODEL / 128, M_TOK / 128);   // (16, 64)

    // QKV projections
    sgemm_tn<<<ggrid, gblk>>>(x, Wq, q, nullptr, M_TOK, DMODEL, DMODEL);
    sgemm_tn<<<ggrid, gblk>>>(x, Wk, k, nullptr, M_TOK, DMODEL, DMODEL);
    sgemm_tn<<<ggrid, gblk>>>(x, Wv, v, nullptr, M_TOK, DMODEL, DMODEL);

    // attention
    static int fa_smem_set = 0;
    int fa_bytes = FA_SMEM_FLOATS * (int)sizeof(float);
    if (!fa_smem_set) {
        cudaFuncSetAttribute(flash_attn,
                             cudaFuncAttributeMaxDynamicSharedMemorySize,
                             fa_bytes);
        fa_smem_set = 1;
    }
    dim3 fgrid(SEQ / 64, NHEADS, BATCH);     // (32, 16, 4)
    flash_attn<<<fgrid, 256, fa_bytes>>>(q, k, v, ctx);

    // output projection + bias
    sgemm_tn<<<ggrid, gblk>>>(ctx, Wo, out, bo, M_TOK, DMODEL, DMODEL);
}